// round 3
// baseline (speedup 1.0000x reference)
#include <cuda_runtime.h>

#define HW 1024

static __device__ __forceinline__ float plogp(float p) {
    return (p > 0.f) ? p * __log2f(p) : 0.f;
}

// Binary entropy of a window with sum s and inverse element count invn.
static __device__ __forceinline__ float went(float s, float invn) {
    float p1 = s * invn;
    float p0 = 1.f - p1;
    return -(plogp(p0) + plogp(p1));
}

__global__ __launch_bounds__(1024, 1)
void slice_windows_entropy_kernel(const float* __restrict__ x, float* __restrict__ out) {
    const int b = blockIdx.z;
    const int tile_r = blockIdx.y * 256;
    const int tile_c = blockIdx.x * 256;
    const int tx = threadIdx.x;   // 0..31 (block col within tile)
    const int ty = threadIdx.y;   // 0..31 (block row within tile)

    __shared__ float s[32][32];   // per-thread k=8 window sums -> pyramid
    __shared__ float acc[8];      // per-CTA entropy sums, one per kernel size

    if (ty == 0 && tx < 8) acc[tx] = 0.f;

    const float* base = x + (size_t)b * HW * HW
                          + (size_t)(tile_r + ty * 8) * HW
                          + (size_t)(tile_c + tx * 8);

    // ---- per-thread 8x8 block: k=2, k=4, k=8 in registers ----
    float e2 = 0.f, e4 = 0.f;
    float s4a = 0.f, s4b = 0.f;   // two k=4 columns accumulating over row pairs
    float s8 = 0.f;

    #pragma unroll
    for (int rp = 0; rp < 4; rp++) {
        const float4* r0 = (const float4*)(base + (size_t)(rp * 2)     * HW);
        const float4* r1 = (const float4*)(base + (size_t)(rp * 2 + 1) * HW);
        float4 a0 = r0[0];
        float4 a1 = r0[1];
        float4 b0 = r1[0];
        float4 b1 = r1[1];

        // four k=2 windows in this 2-row strip
        float w0 = (a0.x + a0.y) + (b0.x + b0.y);
        float w1 = (a0.z + a0.w) + (b0.z + b0.w);
        float w2 = (a1.x + a1.y) + (b1.x + b1.y);
        float w3 = (a1.z + a1.w) + (b1.z + b1.w);

        e2 += went(w0, 0.25f) + went(w1, 0.25f)
            + went(w2, 0.25f) + went(w3, 0.25f);

        s4a += w0 + w1;
        s4b += w2 + w3;
        if (rp & 1) {
            e4 += went(s4a, 1.f / 16.f) + went(s4b, 1.f / 16.f);
            s8 += s4a + s4b;
            s4a = 0.f;
            s4b = 0.f;
        }
    }
    float e8 = went(s8, 1.f / 64.f);

    s[ty][tx] = s8;
    __syncthreads();   // s populated; acc initialized

    // ---- warp reduce e2/e4/e8 (warp == one ty row, lanes == tx) ----
    #pragma unroll
    for (int off = 16; off; off >>= 1) {
        e2 += __shfl_down_sync(0xffffffffu, e2, off);
        e4 += __shfl_down_sync(0xffffffffu, e4, off);
        e8 += __shfl_down_sync(0xffffffffu, e8, off);
    }
    if (tx == 0) {
        atomicAdd(&acc[0], e2);
        atomicAdd(&acc[1], e4);
        atomicAdd(&acc[2], e8);
    }

    // ---- shared-memory pyramid: k=16,32,64,128,256 ----
    float invn = 1.f / 256.f;   // k=16 -> n = 256
    int size = 16;
    #pragma unroll
    for (int lvl = 3; lvl < 8; lvl++) {
        float v = 0.f;
        bool active = (tx < size) && (ty < size);
        if (active) {
            v = s[2 * ty][2 * tx]     + s[2 * ty][2 * tx + 1]
              + s[2 * ty + 1][2 * tx] + s[2 * ty + 1][2 * tx + 1];
        }
        __syncthreads();
        if (active) {
            s[ty][tx] = v;
            atomicAdd(&acc[lvl], went(v, invn));
        }
        __syncthreads();
        size >>= 1;
        invn *= 0.25f;
    }

    // ---- scale by 1/num_windows and accumulate to global output ----
    if (ty == 0 && tx < 8) {
        float k = (float)(2 << tx);                        // 2,4,...,256
        float scale = (k * k) * (1.f / (1024.f * 1024.f)); // = 1/(1024/k)^2
        atomicAdd(&out[b * 8 + tx], acc[tx] * scale);
    }
}

extern "C" void kernel_launch(void* const* d_in, const int* in_sizes, int n_in,
                              void* d_out, int out_size) {
    const float* x = (const float*)d_in[0];
    float* out = (float*)d_out;

    // zero the (32,8) output accumulator (graph-capturable memset node)
    cudaMemsetAsync(out, 0, 32 * 8 * sizeof(float));

    dim3 grid(4, 4, 32);     // 4x4 tiles of 256x256, 32 batch images
    dim3 block(32, 32);      // one thread per 8x8 pixel block
    slice_windows_entropy_kernel<<<grid, block>>>(x, out);
}

// round 7
// speedup vs baseline: 1.0112x; 1.0112x over previous
#include <cuda_runtime.h>

#define HW 1024

static __device__ __forceinline__ float plogp(float p) {
    return (p > 0.f) ? p * __log2f(p) : 0.f;
}

static __device__ __forceinline__ float went(float s, float invn) {
    float p1 = s * invn;
    float p0 = 1.f - p1;
    return -(plogp(p0) + plogp(p1));
}

__global__ __launch_bounds__(1024, 1)
void slice_windows_entropy_kernel(const float* __restrict__ x, float* __restrict__ out) {
    const int b = blockIdx.z;
    const int tile_r = blockIdx.y * 256;
    const int tile_c = blockIdx.x * 256;
    const int tx = threadIdx.x;   // 0..31
    const int ty = threadIdx.y;   // 0..31

    __shared__ float s[32][32];
    __shared__ float acc[8];

    if (ty == 0 && tx < 8) acc[tx] = 0.f;

    const float* base = x + (size_t)b * HW * HW
                          + (size_t)(tile_r + ty * 8) * HW
                          + (size_t)(tile_c + tx * 8);

    // ---- 16 k=2 window sums, loads front-batched in two phases of 8 LDG.128 ----
    // w[wr*4 + wc]: window-row wr in 0..3, window-col wc in 0..3
    float w[16];

    {   // phase 1: rows 0..3 (8 loads issued back-to-back, then pure FADD reduce)
        float4 v[8];
        #pragma unroll
        for (int r = 0; r < 4; r++) {
            const float4* row = (const float4*)(base + (size_t)r * HW);
            v[2 * r]     = row[0];
            v[2 * r + 1] = row[1];
        }
        #pragma unroll
        for (int p = 0; p < 2; p++) {   // row pairs (0,1) and (2,3)
            float4 a0 = v[4 * p], a1 = v[4 * p + 1];
            float4 b0 = v[4 * p + 2], b1 = v[4 * p + 3];
            w[p * 4 + 0] = (a0.x + a0.y) + (b0.x + b0.y);
            w[p * 4 + 1] = (a0.z + a0.w) + (b0.z + b0.w);
            w[p * 4 + 2] = (a1.x + a1.y) + (b1.x + b1.y);
            w[p * 4 + 3] = (a1.z + a1.w) + (b1.z + b1.w);
        }
    }
    {   // phase 2: rows 4..7
        float4 v[8];
        #pragma unroll
        for (int r = 0; r < 4; r++) {
            const float4* row = (const float4*)(base + (size_t)(r + 4) * HW);
            v[2 * r]     = row[0];
            v[2 * r + 1] = row[1];
        }
        #pragma unroll
        for (int p = 0; p < 2; p++) {   // row pairs (4,5) and (6,7)
            float4 a0 = v[4 * p], a1 = v[4 * p + 1];
            float4 b0 = v[4 * p + 2], b1 = v[4 * p + 3];
            w[8 + p * 4 + 0] = (a0.x + a0.y) + (b0.x + b0.y);
            w[8 + p * 4 + 1] = (a0.z + a0.w) + (b0.z + b0.w);
            w[8 + p * 4 + 2] = (a1.x + a1.y) + (b1.x + b1.y);
            w[8 + p * 4 + 3] = (a1.z + a1.w) + (b1.z + b1.w);
        }
    }

    // ---- deferred entropy math (MUFU tail overlaps other warps' loads) ----
    float e2 = 0.f;
    #pragma unroll
    for (int i = 0; i < 16; i++) e2 += went(w[i], 0.25f);

    float e4 = 0.f, s8 = 0.f;
    #pragma unroll
    for (int r4 = 0; r4 < 2; r4++) {
        #pragma unroll
        for (int c4 = 0; c4 < 2; c4++) {
            float s4 = (w[(2 * r4) * 4 + 2 * c4]     + w[(2 * r4) * 4 + 2 * c4 + 1])
                     + (w[(2 * r4 + 1) * 4 + 2 * c4] + w[(2 * r4 + 1) * 4 + 2 * c4 + 1]);
            e4 += went(s4, 1.f / 16.f);
            s8 += s4;
        }
    }
    float e8 = went(s8, 1.f / 64.f);

    s[ty][tx] = s8;
    __syncthreads();

    // ---- warp reduce e2/e4/e8 ----
    #pragma unroll
    for (int off = 16; off; off >>= 1) {
        e2 += __shfl_down_sync(0xffffffffu, e2, off);
        e4 += __shfl_down_sync(0xffffffffu, e4, off);
        e8 += __shfl_down_sync(0xffffffffu, e8, off);
    }
    if (tx == 0) {
        atomicAdd(&acc[0], e2);
        atomicAdd(&acc[1], e4);
        atomicAdd(&acc[2], e8);
    }

    // ---- shared-memory pyramid: k=16,32,64,128,256 ----
    float invn = 1.f / 256.f;
    int size = 16;
    #pragma unroll
    for (int lvl = 3; lvl < 8; lvl++) {
        float v = 0.f;
        bool active = (tx < size) && (ty < size);
        if (active) {
            v = s[2 * ty][2 * tx]     + s[2 * ty][2 * tx + 1]
              + s[2 * ty + 1][2 * tx] + s[2 * ty + 1][2 * tx + 1];
        }
        __syncthreads();
        if (active) {
            s[ty][tx] = v;
            atomicAdd(&acc[lvl], went(v, invn));
        }
        __syncthreads();
        size >>= 1;
        invn *= 0.25f;
    }

    if (ty == 0 && tx < 8) {
        float k = (float)(2 << tx);                        // 2,4,...,256
        float scale = (k * k) * (1.f / (1024.f * 1024.f)); // 1/num_windows
        atomicAdd(&out[b * 8 + tx], acc[tx] * scale);
    }
}

extern "C" void kernel_launch(void* const* d_in, const int* in_sizes, int n_in,
                              void* d_out, int out_size) {
    const float* x = (const float*)d_in[0];
    float* out = (float*)d_out;

    cudaMemsetAsync(out, 0, 32 * 8 * sizeof(float));

    dim3 grid(4, 4, 32);
    dim3 block(32, 32);
    slice_windows_entropy_kernel<<<grid, block>>>(x, out);
}

// round 8
// speedup vs baseline: 1.9668x; 1.9449x over previous
#include <cuda_runtime.h>

#define HW 1024

static __device__ __forceinline__ float plogp(float p) {
    return (p > 0.f) ? p * __log2f(p) : 0.f;
}

static __device__ __forceinline__ float went(float s, float invn) {
    float p1 = s * invn;
    float p0 = 1.f - p1;
    return -(plogp(p0) + plogp(p1));
}

// Grid: (4 strips, 32 images). Block: 256 threads (1D).
// Thread t owns columns [4t, 4t+4) of a 1024x256 strip. Warp w owns columns
// [128w, 128(w+1)) -> every LDG.128 is a fully-contiguous 512B warp access.
__global__ __launch_bounds__(256, 2)
void slice_windows_entropy_kernel(const float* __restrict__ x, float* __restrict__ out) {
    const int b = blockIdx.y;
    const int strip = blockIdx.x;              // 256-row strip
    const int tid = threadIdx.x;               // 0..255
    const int lane = tid & 31;
    const int warp = tid >> 5;

    __shared__ float ws[8];                    // per-warp 128x256 column sums (for k=256)
    __shared__ float acc[8];
    if (tid < 8) acc[tid] = 0.f;

    const float* base = x + (size_t)b * HW * HW + (size_t)strip * 256 * HW + tid * 4;

    float e2 = 0.f, e4 = 0.f, e8 = 0.f, e16 = 0.f, e32 = 0.f, e64 = 0.f, e128 = 0.f;
    float a32 = 0.f, a64 = 0.f, a128 = 0.f, a256 = 0.f;

    // 16 blocks of 16 rows; all 16 row-loads of a block issued back-to-back.
    for (int blk = 0; blk < 16; blk++) {
        float4 v[16];
        #pragma unroll
        for (int r = 0; r < 16; r++)
            v[r] = *(const float4*)(base + (size_t)(blk * 16 + r) * HW);

        float h8[2];
        #pragma unroll
        for (int half = 0; half < 2; half++) {       // 8 rows each
            float s4w[2];
            #pragma unroll
            for (int q = 0; q < 2; q++) {            // 4 rows each
                float sc[2];
                #pragma unroll
                for (int rp = 0; rp < 2; rp++) {     // one 2-row pair
                    float4 a = v[half * 8 + q * 4 + rp * 2];
                    float4 c = v[half * 8 + q * 4 + rp * 2 + 1];
                    float w2a = (a.x + a.y) + (c.x + c.y);
                    float w2b = (a.z + a.w) + (c.z + c.w);
                    e2 += went(w2a, 0.25f) + went(w2b, 0.25f);
                    sc[rp] = w2a + w2b;
                }
                float s4 = sc[0] + sc[1];            // 4x4 window (lane-local)
                e4 += went(s4, 1.f / 16.f);
                s4w[q] = s4;
            }
            float h = s4w[0] + s4w[1];               // lane's 4 cols x 8 rows
            float s8 = h + __shfl_xor_sync(0xffffffffu, h, 1);
            if (!(lane & 1)) e8 += went(s8, 1.f / 64.f);
            h8[half] = h;
        }
        float h16 = h8[0] + h8[1];                   // lane's 4 cols x 16 rows
        {
            float g = h16 + __shfl_xor_sync(0xffffffffu, h16, 1);
            g += __shfl_xor_sync(0xffffffffu, g, 2);
            if (!(lane & 3)) e16 += went(g, 1.f / 256.f);
        }
        a32 += h16; a64 += h16; a128 += h16; a256 += h16;

        if ((blk & 1) == 1) {                        // 32 rows done
            float g = a32;
            g += __shfl_xor_sync(0xffffffffu, g, 1);
            g += __shfl_xor_sync(0xffffffffu, g, 2);
            g += __shfl_xor_sync(0xffffffffu, g, 4);
            if (!(lane & 7)) e32 += went(g, 1.f / 1024.f);
            a32 = 0.f;
        }
        if ((blk & 3) == 3) {                        // 64 rows done
            float g = a64;
            #pragma unroll
            for (int o = 1; o < 16; o <<= 1) g += __shfl_xor_sync(0xffffffffu, g, o);
            if (!(lane & 15)) e64 += went(g, 1.f / 4096.f);
            a64 = 0.f;
        }
        if ((blk & 7) == 7) {                        // 128 rows done
            float g = a128;
            #pragma unroll
            for (int o = 1; o < 32; o <<= 1) g += __shfl_xor_sync(0xffffffffu, g, o);
            if (lane == 0) e128 += went(g, 1.f / 16384.f);
            a128 = 0.f;
        }
    }

    // k=256: warp's 128x256 sum -> smem, pair adjacent warps
    {
        float g = a256;
        #pragma unroll
        for (int o = 1; o < 32; o <<= 1) g += __shfl_xor_sync(0xffffffffu, g, o);
        if (lane == 0) ws[warp] = g;
    }
    __syncthreads();

    // reduce per-lane entropy accumulators (non-leader lanes hold 0 for gated ks)
    float ev[7] = {e2, e4, e8, e16, e32, e64, e128};
    #pragma unroll
    for (int i = 0; i < 7; i++) {
        float g = ev[i];
        #pragma unroll
        for (int o = 1; o < 32; o <<= 1) g += __shfl_xor_sync(0xffffffffu, g, o);
        if (lane == 0) atomicAdd(&acc[i], g);
    }
    if (tid == 0) {
        float e256 = 0.f;
        #pragma unroll
        for (int c = 0; c < 4; c++)
            e256 += went(ws[2 * c] + ws[2 * c + 1], 1.f / 65536.f);
        atomicAdd(&acc[7], e256);
    }
    __syncthreads();

    if (tid < 8) {
        float k = (float)(2 << tid);                        // 2,4,...,256
        float scale = (k * k) * (1.f / (1024.f * 1024.f));  // 1/num_windows
        atomicAdd(&out[b * 8 + tid], acc[tid] * scale);
    }
}

extern "C" void kernel_launch(void* const* d_in, const int* in_sizes, int n_in,
                              void* d_out, int out_size) {
    const float* x = (const float*)d_in[0];
    float* out = (float*)d_out;

    cudaMemsetAsync(out, 0, 32 * 8 * sizeof(float));

    dim3 grid(4, 32);      // 4 strips of 256 rows x 32 images = 128 CTAs (one wave)
    dim3 block(256);
    slice_windows_entropy_kernel<<<grid, block>>>(x, out);
}